// round 15
// baseline (speedup 1.0000x reference)
#include <cuda_runtime.h>
#include <cuda_fp16.h>
#include <math_constants.h>
#include <cstdint>
#include <cstddef>

#define DEMB 768
#define KSEL 32
#define K2   128               // blockmin threshold rank
#define RF   128               // exact-refine count
#define TILE_N 64
#define KC   32                // k elements per chunk
#define NCH  (DEMB / KC)       // 24
#define MAXB 256
#define MAXN 200000
#define MAXT ((MAXN + TILE_N - 1) / TILE_N)   // 3125
#define CCAP 1024
#define NL   13                // blockmins cached per thread (13*256 >= MAXT)

#define A_PITCH 48
#define B_PITCH 48
#define A_BYTES (256 * A_PITCH)    // 12288 per stage
#define B_BYTES (TILE_N * B_PITCH) // 3072 per buffer
#define STAGES 4

// ---- device scratch ----
__device__ __align__(16) uint8_t g_Q8[MAXB * DEMB];
__device__ __align__(16) __half  g_S[(size_t)MAXB * (size_t)MAXN];
__device__ __align__(16) float   g_blkmin[(size_t)MAXB * MAXT];

__device__ __forceinline__ uint32_t smem_u32(const void* p) {
    uint32_t a;
    asm("{ .reg .u64 t; cvta.to.shared.u64 t, %1; cvt.u32.u64 %0, t; }" : "=r"(a) : "l"(p));
    return a;
}
__device__ __forceinline__ void cp16(uint32_t dst, const void* src) {
    asm volatile("cp.async.ca.shared.global [%0], [%1], 16;" :: "r"(dst), "l"(src));
}
#define CP_COMMIT() asm volatile("cp.async.commit_group;" ::: "memory")
#define CP_WAIT2()  asm volatile("cp.async.wait_group 2;" ::: "memory")
#define LDSM4(r0, r1, r2, r3, a) \
    asm volatile("ldmatrix.sync.aligned.m8n8.x4.shared.b16 {%0,%1,%2,%3}, [%4];" \
        : "=r"(r0), "=r"(r1), "=r"(r2), "=r"(r3) : "r"(a))

__device__ __forceinline__ uint32_t pack_e4m3(float f0, float f1, float f2, float f3) {
    uint16_t lo, hi;
    asm("cvt.rn.satfinite.e4m3x2.f32 %0, %1, %2;" : "=h"(lo) : "f"(f1), "f"(f0));
    asm("cvt.rn.satfinite.e4m3x2.f32 %0, %1, %2;" : "=h"(hi) : "f"(f3), "f"(f2));
    return (uint32_t)lo | ((uint32_t)hi << 16);
}
__device__ __forceinline__ void mma_fp8(float* c, const uint32_t* a, const uint32_t* b) {
    asm volatile(
        "mma.sync.aligned.m16n8k32.row.col.f32.e4m3.e4m3.f32 "
        "{%0,%1,%2,%3}, {%4,%5,%6,%7}, {%8,%9}, {%0,%1,%2,%3};"
        : "+f"(c[0]), "+f"(c[1]), "+f"(c[2]), "+f"(c[3])
        : "r"(a[0]), "r"(a[1]), "r"(a[2]), "r"(a[3]), "r"(b[0]), "r"(b[1]));
}
__device__ __forceinline__ unsigned enc(float f) {
    unsigned u = __float_as_uint(f);
    return (u & 0x80000000u) ? ~u : (u | 0x80000000u);
}
__device__ __forceinline__ float dec(unsigned u) {
    u = (u & 0x80000000u) ? (u & 0x7fffffffu) : ~u;
    return __uint_as_float(u);
}
__device__ __forceinline__ unsigned long long mkkey(float v, int idx) {
    return ((unsigned long long)enc(v) << 32) | (unsigned)idx;
}

// ---------------- Q fp32 -> e4m3 (zero-pad to MAXB rows) ----------------
__global__ void convq_kernel(const float* __restrict__ Q, int total) {
    int i = blockIdx.x * blockDim.x + threadIdx.x;
    if (i < MAXB * DEMB / 4) {
        int e = i * 4;
        float4 v = make_float4(0.f, 0.f, 0.f, 0.f);
        if (e < total) v = *(const float4*)&Q[e];
        ((uint32_t*)g_Q8)[i] = pack_e4m3(v.x, v.y, v.z, v.w);
    }
}

// ---------------- FP8 MMA GEMM, M=256 x N-tile=64, 2 CTAs/SM, fp16 out ----------------
__global__ __launch_bounds__(256, 2)
void gemm_fp8_kernel(const float* __restrict__ X, int B, int N, int ntiles)
{
    extern __shared__ __align__(16) char dsm[];
    __shared__ float    x2p[TILE_N];
    __shared__ unsigned bmu[256];

    const int tid  = threadIdx.x;
    const int lane = tid & 31;
    const int warp = tid >> 5;
    const int wm = warp >> 1, wn = warp & 1;
    const int fr = lane >> 2, fc = lane & 3;
    const int n0 = blockIdx.x * TILE_N;

    const uint32_t sb = smem_u32(dsm);
    char* bbuf = dsm + STAGES * A_BYTES;      // 2 fp8 B buffers

    const uint32_t aoff = ((lane & 7) + ((lane >> 3) & 1) * 8) * A_PITCH + ((lane >> 4) & 1) * 16;
    const uint32_t boff = ((lane & 7) + ((lane >> 3) >> 1) * 8) * B_PITCH + ((lane >> 3) & 1) * 16;

    // A cp.async: 256 rows, one row per thread (2 x 16B)
    const char* asrc = (const char*)g_Q8 + (size_t)tid * DEMB;
    const uint32_t adst = sb + tid * A_PITCH;

    // B via registers: thread owns (row = tid>>2, col quarter q = tid&3)
    const int rB = tid >> 2, qB = tid & 3;
    const float* bsrc = &X[(size_t)min(n0 + rB, N - 1) * DEMB + qB * 8];
    const int bwoff = rB * B_PITCH + qB * 8;

    bmu[tid] = 0xFFFFFFFFu;

    // prologue: A stages 0..2
    #pragma unroll
    for (int s = 0; s < 3; s++) {
        cp16(adst + s * A_BYTES, asrc + s * KC);
        cp16(adst + s * A_BYTES + 16, asrc + s * KC + 16);
        CP_COMMIT();
    }

    float x2r = 0.f;

    // chunk 0 -> B[0] (+x2), prefetch chunk 1 regs
    float4 bn0, bn1;
    {
        float4 c0 = *(const float4*)bsrc;
        float4 c1 = *(const float4*)(bsrc + 4);
        uint2 pk;
        pk.x = pack_e4m3(c0.x, c0.y, c0.z, c0.w);
        pk.y = pack_e4m3(c1.x, c1.y, c1.z, c1.w);
        *(uint2*)(bbuf + bwoff) = pk;
        x2r += fmaf(c0.x, c0.x, fmaf(c0.y, c0.y, fmaf(c0.z, c0.z, c0.w * c0.w)));
        x2r += fmaf(c1.x, c1.x, fmaf(c1.y, c1.y, fmaf(c1.z, c1.z, c1.w * c1.w)));
        bn0 = *(const float4*)(bsrc + KC);
        bn1 = *(const float4*)(bsrc + KC + 4);
    }

    float acc[4][4][4];
    #pragma unroll
    for (int mi = 0; mi < 4; mi++)
        #pragma unroll
        for (int ni = 0; ni < 4; ni++)
            #pragma unroll
            for (int r = 0; r < 4; r++) acc[mi][ni][r] = 0.f;

    for (int ch = 0; ch < NCH; ch++) {
        const int st = ch & 1;
        CP_WAIT2();
        __syncthreads();   // A stage ready; B[st] visible; prior reads of B[st^1] done

        // convert prefetched chunk ch+1 -> B[st^1] (overlaps with this chunk's MMAs)
        if (ch + 1 < NCH) {
            uint2 pk;
            pk.x = pack_e4m3(bn0.x, bn0.y, bn0.z, bn0.w);
            pk.y = pack_e4m3(bn1.x, bn1.y, bn1.z, bn1.w);
            *(uint2*)(bbuf + (st ^ 1) * B_BYTES + bwoff) = pk;
            x2r += fmaf(bn0.x, bn0.x, fmaf(bn0.y, bn0.y, fmaf(bn0.z, bn0.z, bn0.w * bn0.w)));
            x2r += fmaf(bn1.x, bn1.x, fmaf(bn1.y, bn1.y, fmaf(bn1.z, bn1.z, bn1.w * bn1.w)));
        }
        if (ch + 2 < NCH) {
            const float* bp = bsrc + (ch + 2) * KC;
            bn0 = *(const float4*)bp;
            bn1 = *(const float4*)(bp + 4);
        }
        if (ch + 3 < NCH) {
            const uint32_t so = ((ch + 3) & 3) * A_BYTES;
            cp16(adst + so, asrc + (ch + 3) * KC);
            cp16(adst + so + 16, asrc + (ch + 3) * KC + 16);
        }
        CP_COMMIT();

        // B fragments: 2x ldmatrix.x4
        const uint32_t Bbu = sb + STAGES * A_BYTES + st * B_BYTES;
        uint32_t bf[4][2];
        #pragma unroll
        for (int p = 0; p < 2; p++)
            LDSM4(bf[2 * p][0], bf[2 * p][1], bf[2 * p + 1][0], bf[2 * p + 1][1],
                  Bbu + (wn * 32 + p * 16) * B_PITCH + boff);

        // A fragments (1 ldmatrix.x4 per mi) + MMAs
        const uint32_t Abu = sb + (ch & 3) * A_BYTES;
        #pragma unroll
        for (int mi = 0; mi < 4; mi++) {
            uint32_t a[4];
            LDSM4(a[0], a[1], a[2], a[3], Abu + (wm * 64 + mi * 16) * A_PITCH + aoff);
            #pragma unroll
            for (int ni = 0; ni < 4; ni++)
                mma_fp8(acc[mi][ni], a, bf[ni]);
        }
    }

    // x2: reduce over the 4 quarter-lanes owning each row
    x2r += __shfl_xor_sync(0xffffffffu, x2r, 1, 4);
    x2r += __shfl_xor_sync(0xffffffffu, x2r, 2, 4);
    if (qB == 0) x2p[rB] = x2r;
    __syncthreads();

    // ---- epilogue: d2 -> fp16 store, blockmin over ROUNDED values ----
    #pragma unroll
    for (int mi = 0; mi < 4; mi++) {
        const int R = wm * 64 + mi * 16 + fr;
        float mn0 = CUDART_INF_F, mn1 = CUDART_INF_F;
        #pragma unroll
        for (int ni = 0; ni < 4; ni++) {
            const int c = wn * 32 + ni * 8 + 2 * fc;
            const int n = n0 + c;
            float x2c = x2p[c], x2d = x2p[c + 1];
            float v0 = fmaf(-2.f, acc[mi][ni][0], x2c);
            float v1 = fmaf(-2.f, acc[mi][ni][1], x2d);
            float v2 = fmaf(-2.f, acc[mi][ni][2], x2c);
            float v3 = fmaf(-2.f, acc[mi][ni][3], x2d);
            __half2 h0 = __floats2half2_rn(v0, v1);
            __half2 h1 = __floats2half2_rn(v2, v3);
            if (R < B)     *(__half2*)&g_S[(size_t)R * N + n]       = h0;
            if (R + 8 < B) *(__half2*)&g_S[(size_t)(R + 8) * N + n] = h1;
            float r0 = __low2float(h0),  r1 = __high2float(h0);
            float r2 = __low2float(h1),  r3 = __high2float(h1);
            mn0 = fminf(mn0, fminf(r0, r1));
            mn1 = fminf(mn1, fminf(r2, r3));
        }
        #pragma unroll
        for (int off = 1; off < 4; off <<= 1) {
            mn0 = fminf(mn0, __shfl_xor_sync(0xffffffffu, mn0, off));
            mn1 = fminf(mn1, __shfl_xor_sync(0xffffffffu, mn1, off));
        }
        if (fc == 0) {
            atomicMin(&bmu[R], enc(mn0));
            atomicMin(&bmu[R + 8], enc(mn1));
        }
    }
    __syncthreads();
    g_blkmin[(size_t)tid * ntiles + blockIdx.x] = dec(bmu[tid]);
}

// ---------------- select: approx sort -> refine top-RF -> exact sort ----------------
__global__ __launch_bounds__(512)
void select_kernel(const float* __restrict__ Q, const int* __restrict__ qsys,
                   const float* __restrict__ X, const float* __restrict__ Y,
                   const int* __restrict__ sys, const float* __restrict__ W,
                   const float* __restrict__ bias, float* __restrict__ out,
                   int B, int N, int ntiles)
{
    __shared__ float qs[2][DEMB];
    __shared__ unsigned long long buf[2][CCAP];
    __shared__ int   blist[2][CCAP];
    __shared__ float red[2][8];
    __shared__ int   wcnt[2][2][8];
    __shared__ int   sh_cnt[2], sh_nblk[2];

    const int tid  = threadIdx.x;
    const int half = tid >> 8;
    const int htid = tid & 255;
    const int hw   = htid >> 5;
    const int lane = tid & 31;
    const int hbar = half + 1;
    const int b    = blockIdx.x * 2 + half;

    #define HBAR() asm volatile("bar.sync %0, 256;" :: "r"(hbar) : "memory")

    // ---- query row + q2 ----
    float q2p = 0.f;
    for (int k = htid; k < DEMB; k += 256) {
        float v = Q[(size_t)b * DEMB + k];
        qs[half][k] = v; q2p = fmaf(v, v, q2p);
    }
    #pragma unroll
    for (int off = 16; off > 0; off >>= 1) q2p += __shfl_xor_sync(0xffffffffu, q2p, off);
    if (lane == 0) red[half][hw] = q2p;
    if (htid == 0) { sh_cnt[half] = 0; sh_nblk[half] = 0; }
    HBAR();
    float q2 = 0.f;
    #pragma unroll
    for (int w = 0; w < 8; w++) q2 += red[half][w];

    // ---- cache blockmins (encoded) ----
    const float* bmrow = &g_blkmin[(size_t)b * ntiles];
    uint32_t loc[NL];
    #pragma unroll
    for (int i = 0; i < NL; i++) {
        int idx = i * 256 + htid;
        loc[i] = (idx < ntiles) ? enc(bmrow[idx]) : 0xFFFFFFFFu;
    }

    // ---- bitwise binary search for t0enc = K2-th smallest (1 barrier/bit) ----
    uint32_t r = 0;
    for (int bitp = 31; bitp >= 0; bitp--) {
        const int pp = bitp & 1;
        uint32_t trial = r | (1u << bitp);
        int c = 0;
        #pragma unroll
        for (int i = 0; i < NL; i++) c += (loc[i] < trial);
        #pragma unroll
        for (int off = 16; off > 0; off >>= 1) c += __shfl_xor_sync(0xffffffffu, c, off);
        if (lane == 0) wcnt[half][pp][hw] = c;
        HBAR();
        int tot = 0;
        #pragma unroll
        for (int w = 0; w < 8; w++) tot += wcnt[half][pp][w];
        if (tot < K2) r = trial;
    }
    const uint32_t t0enc = r;
    const float t0 = dec(t0enc);

    // ---- qualifying blocks ----
    #pragma unroll
    for (int i = 0; i < NL; i++) {
        int idx = i * 256 + htid;
        if (idx < ntiles && loc[i] <= t0enc) {
            int p = atomicAdd(&sh_nblk[half], 1);
            if (p < CCAP) blist[half][p] = idx;
        }
    }
    HBAR();
    int nblk = sh_nblk[half]; if (nblk > CCAP) nblk = CCAP;

    // init key arena before gather
    for (int i = htid; i < CCAP; i += 256) buf[half][i] = ~0ULL;
    HBAR();

    // ---- gather approx keys (fp16 value, idx) ----
    const __half* srow = &g_S[(size_t)b * N];
    for (int e = htid; e < nblk * TILE_N; e += 256) {
        int blk = blist[half][e >> 6];
        int n = blk * TILE_N + (e & (TILE_N - 1));
        if (n < N) {
            float v = __half2float(srow[n]);
            if (v <= t0) {
                int p = atomicAdd(&sh_cnt[half], 1);
                if (p < CCAP) buf[half][p] = mkkey(v, n);
            }
        }
    }
    HBAR();
    int cnt = sh_cnt[half]; if (cnt > CCAP) cnt = CCAP;

    // ---- bitonic sort approx keys ascending ----
    int P = RF; while (P < cnt) P <<= 1;
    for (int k = 2; k <= P; k <<= 1)
        for (int j = k >> 1; j > 0; j >>= 1) {
            for (int i = htid; i < P; i += 256) {
                int ixj = i ^ j;
                if (ixj > i) {
                    unsigned long long a = buf[half][i], c = buf[half][ixj];
                    if ((a > c) == ((i & k) == 0)) { buf[half][i] = c; buf[half][ixj] = a; }
                }
            }
            HBAR();
        }

    // ---- exact fp32 refine of top-RF approx candidates (in place) ----
    const int rfn = min(cnt, RF);
    const float4* qs4 = (const float4*)qs[half];
    for (int c = hw; c < rfn; c += 8) {
        const int idx = (int)(buf[half][c] & 0xffffffffu);
        const float4* xr4 = (const float4*)&X[(size_t)idx * DEMB];
        float dot = 0.f, xx = 0.f;
        #pragma unroll
        for (int k = lane; k < DEMB / 4; k += 32) {
            float4 xv = xr4[k];
            float4 qv = qs4[k];
            dot = fmaf(xv.x, qv.x, fmaf(xv.y, qv.y, fmaf(xv.z, qv.z, fmaf(xv.w, qv.w, dot))));
            xx  = fmaf(xv.x, xv.x, fmaf(xv.y, xv.y, fmaf(xv.z, xv.z, fmaf(xv.w, xv.w, xx))));
        }
        #pragma unroll
        for (int off = 16; off > 0; off >>= 1) {
            dot += __shfl_xor_sync(0xffffffffu, dot, off);
            xx  += __shfl_xor_sync(0xffffffffu, xx,  off);
        }
        if (lane == 0) buf[half][c] = mkkey(fmaf(-2.f, dot, q2 + xx), idx);
    }
    // pad tail of the RF window
    for (int i = htid; i < RF; i += 256)
        if (i >= rfn) buf[half][i] = ~0ULL;
    HBAR();

    // ---- bitonic sort the RF exact keys ----
    for (int k = 2; k <= RF; k <<= 1)
        for (int j = k >> 1; j > 0; j >>= 1) {
            for (int i = htid; i < RF; i += 256) {
                int ixj = i ^ j;
                if (ixj > i) {
                    unsigned long long a = buf[half][i], c = buf[half][ixj];
                    if ((a > c) == ((i & k) == 0)) { buf[half][i] = c; buf[half][ixj] = a; }
                }
            }
            HBAR();
        }

    // ---- local layer + prefix softmax ----
    if (htid < KSEL) {
        unsigned long long key = buf[half][htid];
        float d2v = dec((unsigned)(key >> 32));
        int   idx = (int)(key & 0xffffffffu);
        float sc  = Y[idx];
        float nd  = (sys[idx] == qsys[b]) ? fmaf(d2v, W[1], bias[1]) : fmaf(d2v, W[0], bias[0]);
        float neg = -nd;
        float mmax = neg;
        #pragma unroll
        for (int off = 16; off > 0; off >>= 1)
            mmax = fmaxf(mmax, __shfl_xor_sync(0xffffffffu, mmax, off));
        float w  = expf(neg - mmax);
        float ws = w * sc;
        float cw = w, cws = ws;
        #pragma unroll
        for (int off = 1; off < KSEL; off <<= 1) {
            float tw  = __shfl_up_sync(0xffffffffu, cw,  off);
            float tws = __shfl_up_sync(0xffffffffu, cws, off);
            if (lane >= off) { cw += tw; cws += tws; }
        }
        out[(size_t)b * KSEL + htid] = nd;
        out[(size_t)B * KSEL + (size_t)b * KSEL + htid] = cws / cw;
    }
    #undef HBAR
}

extern "C" void kernel_launch(void* const* d_in, const int* in_sizes, int n_in,
                              void* d_out, int out_size)
{
    const float* Q    = (const float*)d_in[0];
    const int*   qsys = (const int*)  d_in[1];
    const float* X    = (const float*)d_in[2];
    const float* Y    = (const float*)d_in[3];
    const int*   sys  = (const int*)  d_in[4];
    const float* W    = (const float*)d_in[5];
    const float* bias = (const float*)d_in[6];
    float* out = (float*)d_out;

    int B = in_sizes[1];
    int N = in_sizes[3];
    int ntiles = (N + TILE_N - 1) / TILE_N;

    const int smem = STAGES * A_BYTES + 2 * B_BYTES;   // 55296
    cudaFuncSetAttribute(gemm_fp8_kernel, cudaFuncAttributeMaxDynamicSharedMemorySize, smem);

    convq_kernel<<<(MAXB * DEMB / 4 + 255) / 256, 256>>>(Q, B * DEMB);
    gemm_fp8_kernel<<<ntiles, 256, smem>>>(X, B, N, ntiles);
    select_kernel<<<(B + 1) / 2, 512>>>(Q, qsys, X, Y, sys, W, bias, out, B, N, ntiles);
}

// round 16
// speedup vs baseline: 1.0636x; 1.0636x over previous
#include <cuda_runtime.h>
#include <cuda_fp16.h>
#include <math_constants.h>
#include <cstdint>
#include <cstddef>

#define DEMB 768
#define KSEL 32
#define K2   128               // blockmin threshold rank
#define TILE_N 64
#define KC   32                // k elements per chunk
#define NCH  (DEMB / KC)       // 24
#define MAXB 256
#define MAXN 200000
#define MAXT ((MAXN + TILE_N - 1) / TILE_N)   // 3125
#define CCAP 1024
#define NL   13                // blockmins cached per thread (13*256 >= MAXT)

#define A_PITCH 48
#define B_PITCH 48
#define A_BYTES (256 * A_PITCH)    // 12288 per stage
#define B_BYTES (TILE_N * B_PITCH) // 3072 per buffer
#define STAGES 4

// ---- device scratch ----
__device__ __align__(16) uint8_t g_Q8[MAXB * DEMB];
__device__ __align__(16) __half  g_S[(size_t)MAXB * (size_t)MAXN];
__device__ __align__(16) float   g_blkmin[(size_t)MAXB * MAXT];

__device__ __forceinline__ uint32_t smem_u32(const void* p) {
    uint32_t a;
    asm("{ .reg .u64 t; cvta.to.shared.u64 t, %1; cvt.u32.u64 %0, t; }" : "=r"(a) : "l"(p));
    return a;
}
__device__ __forceinline__ void cp16(uint32_t dst, const void* src) {
    asm volatile("cp.async.ca.shared.global [%0], [%1], 16;" :: "r"(dst), "l"(src));
}
#define CP_COMMIT() asm volatile("cp.async.commit_group;" ::: "memory")
#define CP_WAIT2()  asm volatile("cp.async.wait_group 2;" ::: "memory")
#define LDSM4(r0, r1, r2, r3, a) \
    asm volatile("ldmatrix.sync.aligned.m8n8.x4.shared.b16 {%0,%1,%2,%3}, [%4];" \
        : "=r"(r0), "=r"(r1), "=r"(r2), "=r"(r3) : "r"(a))

__device__ __forceinline__ uint32_t pack_e4m3(float f0, float f1, float f2, float f3) {
    uint16_t lo, hi;
    asm("cvt.rn.satfinite.e4m3x2.f32 %0, %1, %2;" : "=h"(lo) : "f"(f1), "f"(f0));
    asm("cvt.rn.satfinite.e4m3x2.f32 %0, %1, %2;" : "=h"(hi) : "f"(f3), "f"(f2));
    return (uint32_t)lo | ((uint32_t)hi << 16);
}
__device__ __forceinline__ void mma_fp8(float* c, const uint32_t* a, const uint32_t* b) {
    asm volatile(
        "mma.sync.aligned.m16n8k32.row.col.f32.e4m3.e4m3.f32 "
        "{%0,%1,%2,%3}, {%4,%5,%6,%7}, {%8,%9}, {%0,%1,%2,%3};"
        : "+f"(c[0]), "+f"(c[1]), "+f"(c[2]), "+f"(c[3])
        : "r"(a[0]), "r"(a[1]), "r"(a[2]), "r"(a[3]), "r"(b[0]), "r"(b[1]));
}
__device__ __forceinline__ unsigned enc(float f) {
    unsigned u = __float_as_uint(f);
    return (u & 0x80000000u) ? ~u : (u | 0x80000000u);
}
__device__ __forceinline__ float dec(unsigned u) {
    u = (u & 0x80000000u) ? (u & 0x7fffffffu) : ~u;
    return __uint_as_float(u);
}
__device__ __forceinline__ unsigned long long mkkey(float v, int idx) {
    return ((unsigned long long)enc(v) << 32) | (unsigned)idx;
}

// ---------------- Q fp32 -> e4m3 (zero-pad to MAXB rows) ----------------
__global__ void convq_kernel(const float* __restrict__ Q, int total) {
    int i = blockIdx.x * blockDim.x + threadIdx.x;
    if (i < MAXB * DEMB / 4) {
        int e = i * 4;
        float4 v = make_float4(0.f, 0.f, 0.f, 0.f);
        if (e < total) v = *(const float4*)&Q[e];
        ((uint32_t*)g_Q8)[i] = pack_e4m3(v.x, v.y, v.z, v.w);
    }
}

// ---------------- FP8 MMA GEMM, M=256 x N-tile=64, 2 CTAs/SM, fp16 out ----------------
__global__ __launch_bounds__(256, 2)
void gemm_fp8_kernel(const float* __restrict__ X, int B, int N, int ntiles)
{
    extern __shared__ __align__(16) char dsm[];
    __shared__ float    x2p[TILE_N];
    __shared__ unsigned bmu[256];

    const int tid  = threadIdx.x;
    const int lane = tid & 31;
    const int warp = tid >> 5;
    const int wm = warp >> 1, wn = warp & 1;
    const int fr = lane >> 2, fc = lane & 3;
    const int n0 = blockIdx.x * TILE_N;

    const uint32_t sb = smem_u32(dsm);
    char* bbuf = dsm + STAGES * A_BYTES;      // 2 fp8 B buffers

    const uint32_t aoff = ((lane & 7) + ((lane >> 3) & 1) * 8) * A_PITCH + ((lane >> 4) & 1) * 16;
    const uint32_t boff = ((lane & 7) + ((lane >> 3) >> 1) * 8) * B_PITCH + ((lane >> 3) & 1) * 16;

    // A cp.async: 256 rows, one row per thread (2 x 16B)
    const char* asrc = (const char*)g_Q8 + (size_t)tid * DEMB;
    const uint32_t adst = sb + tid * A_PITCH;

    // B via registers: thread owns (row = tid>>2, col quarter q = tid&3)
    const int rB = tid >> 2, qB = tid & 3;
    const float* bsrc = &X[(size_t)min(n0 + rB, N - 1) * DEMB + qB * 8];
    const int bwoff = rB * B_PITCH + qB * 8;

    bmu[tid] = 0xFFFFFFFFu;

    // prologue: A stages 0..2
    #pragma unroll
    for (int s = 0; s < 3; s++) {
        cp16(adst + s * A_BYTES, asrc + s * KC);
        cp16(adst + s * A_BYTES + 16, asrc + s * KC + 16);
        CP_COMMIT();
    }

    float x2r = 0.f;

    // chunk 0 -> B[0] (+x2), prefetch chunk 1 regs
    float4 bn0, bn1;
    {
        float4 c0 = *(const float4*)bsrc;
        float4 c1 = *(const float4*)(bsrc + 4);
        uint2 pk;
        pk.x = pack_e4m3(c0.x, c0.y, c0.z, c0.w);
        pk.y = pack_e4m3(c1.x, c1.y, c1.z, c1.w);
        *(uint2*)(bbuf + bwoff) = pk;
        x2r += fmaf(c0.x, c0.x, fmaf(c0.y, c0.y, fmaf(c0.z, c0.z, c0.w * c0.w)));
        x2r += fmaf(c1.x, c1.x, fmaf(c1.y, c1.y, fmaf(c1.z, c1.z, c1.w * c1.w)));
        bn0 = *(const float4*)(bsrc + KC);
        bn1 = *(const float4*)(bsrc + KC + 4);
    }

    float acc[4][4][4];
    #pragma unroll
    for (int mi = 0; mi < 4; mi++)
        #pragma unroll
        for (int ni = 0; ni < 4; ni++)
            #pragma unroll
            for (int r = 0; r < 4; r++) acc[mi][ni][r] = 0.f;

    for (int ch = 0; ch < NCH; ch++) {
        const int st = ch & 1;
        CP_WAIT2();
        __syncthreads();   // A stage ready; B[st] visible; prior reads of B[st^1] done

        // convert prefetched chunk ch+1 -> B[st^1] (overlaps with this chunk's MMAs)
        if (ch + 1 < NCH) {
            uint2 pk;
            pk.x = pack_e4m3(bn0.x, bn0.y, bn0.z, bn0.w);
            pk.y = pack_e4m3(bn1.x, bn1.y, bn1.z, bn1.w);
            *(uint2*)(bbuf + (st ^ 1) * B_BYTES + bwoff) = pk;
            x2r += fmaf(bn0.x, bn0.x, fmaf(bn0.y, bn0.y, fmaf(bn0.z, bn0.z, bn0.w * bn0.w)));
            x2r += fmaf(bn1.x, bn1.x, fmaf(bn1.y, bn1.y, fmaf(bn1.z, bn1.z, bn1.w * bn1.w)));
        }
        if (ch + 2 < NCH) {
            const float* bp = bsrc + (ch + 2) * KC;
            bn0 = *(const float4*)bp;
            bn1 = *(const float4*)(bp + 4);
        }
        if (ch + 3 < NCH) {
            const uint32_t so = ((ch + 3) & 3) * A_BYTES;
            cp16(adst + so, asrc + (ch + 3) * KC);
            cp16(adst + so + 16, asrc + (ch + 3) * KC + 16);
        }
        CP_COMMIT();

        // B fragments: 2x ldmatrix.x4
        const uint32_t Bbu = sb + STAGES * A_BYTES + st * B_BYTES;
        uint32_t bf[4][2];
        #pragma unroll
        for (int p = 0; p < 2; p++)
            LDSM4(bf[2 * p][0], bf[2 * p][1], bf[2 * p + 1][0], bf[2 * p + 1][1],
                  Bbu + (wn * 32 + p * 16) * B_PITCH + boff);

        // A fragments (1 ldmatrix.x4 per mi) + MMAs
        const uint32_t Abu = sb + (ch & 3) * A_BYTES;
        #pragma unroll
        for (int mi = 0; mi < 4; mi++) {
            uint32_t a[4];
            LDSM4(a[0], a[1], a[2], a[3], Abu + (wm * 64 + mi * 16) * A_PITCH + aoff);
            #pragma unroll
            for (int ni = 0; ni < 4; ni++)
                mma_fp8(acc[mi][ni], a, bf[ni]);
        }
    }

    // x2: reduce over the 4 quarter-lanes owning each row
    x2r += __shfl_xor_sync(0xffffffffu, x2r, 1, 4);
    x2r += __shfl_xor_sync(0xffffffffu, x2r, 2, 4);
    if (qB == 0) x2p[rB] = x2r;
    __syncthreads();

    // ---- epilogue: d2 -> fp16 store, blockmin over ROUNDED values ----
    #pragma unroll
    for (int mi = 0; mi < 4; mi++) {
        const int R = wm * 64 + mi * 16 + fr;
        float mn0 = CUDART_INF_F, mn1 = CUDART_INF_F;
        #pragma unroll
        for (int ni = 0; ni < 4; ni++) {
            const int c = wn * 32 + ni * 8 + 2 * fc;
            const int n = n0 + c;
            float x2c = x2p[c], x2d = x2p[c + 1];
            float v0 = fmaf(-2.f, acc[mi][ni][0], x2c);
            float v1 = fmaf(-2.f, acc[mi][ni][1], x2d);
            float v2 = fmaf(-2.f, acc[mi][ni][2], x2c);
            float v3 = fmaf(-2.f, acc[mi][ni][3], x2d);
            __half2 h0 = __floats2half2_rn(v0, v1);
            __half2 h1 = __floats2half2_rn(v2, v3);
            if (R < B)     *(__half2*)&g_S[(size_t)R * N + n]       = h0;
            if (R + 8 < B) *(__half2*)&g_S[(size_t)(R + 8) * N + n] = h1;
            float r0 = __low2float(h0),  r1 = __high2float(h0);
            float r2 = __low2float(h1),  r3 = __high2float(h1);
            mn0 = fminf(mn0, fminf(r0, r1));
            mn1 = fminf(mn1, fminf(r2, r3));
        }
        #pragma unroll
        for (int off = 1; off < 4; off <<= 1) {
            mn0 = fminf(mn0, __shfl_xor_sync(0xffffffffu, mn0, off));
            mn1 = fminf(mn1, __shfl_xor_sync(0xffffffffu, mn1, off));
        }
        if (fc == 0) {
            atomicMin(&bmu[R], enc(mn0));
            atomicMin(&bmu[R + 8], enc(mn1));
        }
    }
    __syncthreads();
    g_blkmin[(size_t)tid * ntiles + blockIdx.x] = dec(bmu[tid]);
}

// ---------------- select: binary-search t0 -> gather -> refine ALL -> exact sort ----------------
__global__ __launch_bounds__(512)
void select_kernel(const float* __restrict__ Q, const int* __restrict__ qsys,
                   const float* __restrict__ X, const float* __restrict__ Y,
                   const int* __restrict__ sys, const float* __restrict__ W,
                   const float* __restrict__ bias, float* __restrict__ out,
                   int B, int N, int ntiles)
{
    __shared__ float qs[2][DEMB];
    __shared__ unsigned long long buf[2][CCAP];
    __shared__ int   cand[2][CCAP];
    __shared__ int   blist[2][CCAP];
    __shared__ float red[2][8];
    __shared__ int   wcnt[2][2][8];
    __shared__ int   sh_cnt[2], sh_nblk[2];

    const int tid  = threadIdx.x;
    const int half = tid >> 8;
    const int htid = tid & 255;
    const int hw   = htid >> 5;
    const int lane = tid & 31;
    const int hbar = half + 1;
    const int b    = blockIdx.x * 2 + half;

    #define HBAR() asm volatile("bar.sync %0, 256;" :: "r"(hbar) : "memory")

    // ---- query row + q2 ----
    float q2p = 0.f;
    for (int k = htid; k < DEMB; k += 256) {
        float v = Q[(size_t)b * DEMB + k];
        qs[half][k] = v; q2p = fmaf(v, v, q2p);
    }
    #pragma unroll
    for (int off = 16; off > 0; off >>= 1) q2p += __shfl_xor_sync(0xffffffffu, q2p, off);
    if (lane == 0) red[half][hw] = q2p;
    if (htid == 0) { sh_cnt[half] = 0; sh_nblk[half] = 0; }
    HBAR();
    float q2 = 0.f;
    #pragma unroll
    for (int w = 0; w < 8; w++) q2 += red[half][w];

    // ---- cache blockmins (encoded) ----
    const float* bmrow = &g_blkmin[(size_t)b * ntiles];
    uint32_t loc[NL];
    #pragma unroll
    for (int i = 0; i < NL; i++) {
        int idx = i * 256 + htid;
        loc[i] = (idx < ntiles) ? enc(bmrow[idx]) : 0xFFFFFFFFu;
    }

    // ---- bitwise binary search for t0enc = K2-th smallest (1 barrier/bit) ----
    uint32_t r = 0;
    for (int bitp = 31; bitp >= 0; bitp--) {
        const int pp = bitp & 1;
        uint32_t trial = r | (1u << bitp);
        int c = 0;
        #pragma unroll
        for (int i = 0; i < NL; i++) c += (loc[i] < trial);
        #pragma unroll
        for (int off = 16; off > 0; off >>= 1) c += __shfl_xor_sync(0xffffffffu, c, off);
        if (lane == 0) wcnt[half][pp][hw] = c;
        HBAR();
        int tot = 0;
        #pragma unroll
        for (int w = 0; w < 8; w++) tot += wcnt[half][pp][w];
        if (tot < K2) r = trial;
    }
    const uint32_t t0enc = r;
    const float t0 = dec(t0enc);

    // ---- qualifying blocks ----
    #pragma unroll
    for (int i = 0; i < NL; i++) {
        int idx = i * 256 + htid;
        if (idx < ntiles && loc[i] <= t0enc) {
            int p = atomicAdd(&sh_nblk[half], 1);
            if (p < CCAP) blist[half][p] = idx;
        }
    }
    HBAR();
    int nblk = sh_nblk[half]; if (nblk > CCAP) nblk = CCAP;

    // ---- gather candidate indices (fp16 values <= t0; tiles always full) ----
    const __half* srow = &g_S[(size_t)b * N];
    for (int e = htid; e < nblk * TILE_N; e += 256) {
        int blk = blist[half][e >> 6];
        int n = blk * TILE_N + (e & (TILE_N - 1));
        float v = __half2float(srow[n]);
        if (v <= t0) {
            int p = atomicAdd(&sh_cnt[half], 1);
            if (p < CCAP) cand[half][p] = n;
        }
    }
    HBAR();
    int cnt = sh_cnt[half]; if (cnt > CCAP) cnt = CCAP;

    int P = 64; while (P < cnt) P <<= 1;
    for (int i = htid; i < P; i += 256) buf[half][i] = ~0ULL;
    HBAR();

    // ---- exact fp32 refine of ALL candidates (float4) ----
    const float4* qs4 = (const float4*)qs[half];
    for (int c = hw; c < cnt; c += 8) {
        const int idx = cand[half][c];
        const float4* xr4 = (const float4*)&X[(size_t)idx * DEMB];
        float dot = 0.f, xx = 0.f;
        #pragma unroll
        for (int k = lane; k < DEMB / 4; k += 32) {
            float4 xv = xr4[k];
            float4 qv = qs4[k];
            dot = fmaf(xv.x, qv.x, fmaf(xv.y, qv.y, fmaf(xv.z, qv.z, fmaf(xv.w, qv.w, dot))));
            xx  = fmaf(xv.x, xv.x, fmaf(xv.y, xv.y, fmaf(xv.z, xv.z, fmaf(xv.w, xv.w, xx))));
        }
        #pragma unroll
        for (int off = 16; off > 0; off >>= 1) {
            dot += __shfl_xor_sync(0xffffffffu, dot, off);
            xx  += __shfl_xor_sync(0xffffffffu, xx,  off);
        }
        if (lane == 0) buf[half][c] = mkkey(fmaf(-2.f, dot, q2 + xx), idx);
    }
    HBAR();

    // ---- bitonic sort exact keys ascending ----
    for (int k = 2; k <= P; k <<= 1)
        for (int j = k >> 1; j > 0; j >>= 1) {
            for (int i = htid; i < P; i += 256) {
                int ixj = i ^ j;
                if (ixj > i) {
                    unsigned long long a = buf[half][i], c = buf[half][ixj];
                    if ((a > c) == ((i & k) == 0)) { buf[half][i] = c; buf[half][ixj] = a; }
                }
            }
            HBAR();
        }

    // ---- local layer + prefix softmax ----
    if (htid < KSEL) {
        unsigned long long key = buf[half][htid];
        float d2v = dec((unsigned)(key >> 32));
        int   idx = (int)(key & 0xffffffffu);
        float sc  = Y[idx];
        float nd  = (sys[idx] == qsys[b]) ? fmaf(d2v, W[1], bias[1]) : fmaf(d2v, W[0], bias[0]);
        float neg = -nd;
        float mmax = neg;
        #pragma unroll
        for (int off = 16; off > 0; off >>= 1)
            mmax = fmaxf(mmax, __shfl_xor_sync(0xffffffffu, mmax, off));
        float w  = expf(neg - mmax);
        float ws = w * sc;
        float cw = w, cws = ws;
        #pragma unroll
        for (int off = 1; off < KSEL; off <<= 1) {
            float tw  = __shfl_up_sync(0xffffffffu, cw,  off);
            float tws = __shfl_up_sync(0xffffffffu, cws, off);
            if (lane >= off) { cw += tw; cws += tws; }
        }
        out[(size_t)b * KSEL + htid] = nd;
        out[(size_t)B * KSEL + (size_t)b * KSEL + htid] = cws / cw;
    }
    #undef HBAR
}

extern "C" void kernel_launch(void* const* d_in, const int* in_sizes, int n_in,
                              void* d_out, int out_size)
{
    const float* Q    = (const float*)d_in[0];
    const int*   qsys = (const int*)  d_in[1];
    const float* X    = (const float*)d_in[2];
    const float* Y    = (const float*)d_in[3];
    const int*   sys  = (const int*)  d_in[4];
    const float* W    = (const float*)d_in[5];
    const float* bias = (const float*)d_in[6];
    float* out = (float*)d_out;

    int B = in_sizes[1];
    int N = in_sizes[3];
    int ntiles = (N + TILE_N - 1) / TILE_N;

    const int smem = STAGES * A_BYTES + 2 * B_BYTES;   // 55296
    cudaFuncSetAttribute(gemm_fp8_kernel, cudaFuncAttributeMaxDynamicSharedMemorySize, smem);

    convq_kernel<<<(MAXB * DEMB / 4 + 255) / 256, 256>>>(Q, B * DEMB);
    gemm_fp8_kernel<<<ntiles, 256, smem>>>(X, B, N, ntiles);
    select_kernel<<<(B + 1) / 2, 512>>>(Q, qsys, X, Y, sys, W, bias, out, B, N, ntiles);
}